// round 13
// baseline (speedup 1.0000x reference)
#include <cuda_runtime.h>
#include <cuda_bf16.h>
#include <cstdint>

#define D 128          // feature dim
#define H 16           // hidden dim
#define NMAX 100000    // max nodes (scratch sizing)

// Per-node projections P[n][k]: k in [0,16) = z[n] @ W1[0:128,:],
// k in [16,32) = z[n] @ W1[128:256,:] + b1[k-16]  (b1 folded in).
__device__ float g_P[(size_t)NMAX * 32];

// ---------------------------------------------------------------------------
// Kernel 1: P = [z @ W1a , z @ W1b + b1]
// Block = 256 threads = 8 warps; 64 nodes/block, 8 nodes/warp; smem 48KB ->
// 4 CTAs/SM (32 warps). lane = output k. W staged as wt4[d4][k] (contiguous
// in k -> conflict-free). z row-major; main-loop z reads are uniform
// broadcasts (1 crossbar phase). fma.rn.f32x2 with operands loaded directly
// into b64 pairs via ld.shared.v2.b64 (no mov.b64 packing).
// Measured ~27us in this exact configuration (R11/R12 decomposition).
// ---------------------------------------------------------------------------
__global__ __launch_bounds__(256) void proj_kernel(
    const float* __restrict__ z,
    const float* __restrict__ W1,
    const float* __restrict__ b1,
    int N)
{
    extern __shared__ float smem[];
    float*  zs  = smem;                      // [64][128]  32KB
    float4* wt4 = (float4*)(smem + 64 * D);  // [32 d4][32 k] 16KB

    const int tid = threadIdx.x;
    const int nb  = blockIdx.x * 64;

    // Stage W transposed+vectorized: wt4[d4*32 + k] = (w(k,4d4..4d4+3))
    for (int idx = tid; idx < 32 * 32; idx += 256) {
        int d4 = idx >> 5;
        int k  = idx & 31;
        int d0 = d4 * 4;
        float4 w;
        if (k < 16) {
            w.x = W1[(d0 + 0) * H + k];
            w.y = W1[(d0 + 1) * H + k];
            w.z = W1[(d0 + 2) * H + k];
            w.w = W1[(d0 + 3) * H + k];
        } else {
            int kk = k - 16;
            w.x = W1[(D + d0 + 0) * H + kk];
            w.y = W1[(D + d0 + 1) * H + kk];
            w.z = W1[(D + d0 + 2) * H + kk];
            w.w = W1[(D + d0 + 3) * H + kk];
        }
        wt4[idx] = w;
    }

    // Stage up to 64 z rows (coalesced float4)
    {
        const float4* zg = (const float4*)(z + (size_t)nb * D);
        float4* zs4 = (float4*)zs;
        #pragma unroll
        for (int it = 0; it < 8; it++) {
            int idx = it * 256 + tid;
            int r = idx >> 5;
            if (nb + r < N) zs4[idx] = zg[idx];
            else            zs4[idx] = make_float4(0.f, 0.f, 0.f, 0.f);
        }
    }
    __syncthreads();

    const int lane = tid & 31;          // output index k
    const int warp = tid >> 5;
    const int n0   = warp * 8;          // 8 nodes per warp

    unsigned long long acc[8];
    #pragma unroll
    for (int j = 0; j < 8; j++) acc[j] = 0ULL;

    const unsigned int zsh = (unsigned int)__cvta_generic_to_shared(zs + n0 * D);
    const unsigned int wsh = (unsigned int)__cvta_generic_to_shared(wt4) + lane * 16u;

    #pragma unroll 8
    for (int d4 = 0; d4 < 32; d4++) {
        unsigned long long wlo, whi;
        asm("ld.shared.v2.b64 {%0, %1}, [%2];"
            : "=l"(wlo), "=l"(whi) : "r"(wsh + d4 * 512u));   // conflict-free
        #pragma unroll
        for (int j = 0; j < 8; j++) {
            unsigned long long vlo, vhi;
            asm("ld.shared.v2.b64 {%0, %1}, [%2];"
                : "=l"(vlo), "=l"(vhi)
                : "r"(zsh + j * 512u + d4 * 16u));            // broadcast
            asm("fma.rn.f32x2 %0, %1, %2, %0;" : "+l"(acc[j]) : "l"(vlo), "l"(wlo));
            asm("fma.rn.f32x2 %0, %1, %2, %0;" : "+l"(acc[j]) : "l"(vhi), "l"(whi));
        }
    }

    float bb = (lane >= 16) ? __ldg(b1 + lane - 16) : 0.f;

    #pragma unroll
    for (int j = 0; j < 8; j++) {
        int n = nb + n0 + j;
        if (n < N) {
            float lo, hi;
            asm("mov.b64 {%0, %1}, %2;" : "=f"(lo), "=f"(hi) : "l"(acc[j]));
            g_P[(size_t)n * 32 + lane] = lo + hi + bb;
        }
    }
}

// ---------------------------------------------------------------------------
// Kernel 2 (R10-proven fused edge): 8 lanes per edge (4 edges per warp).
//   adj_logits[e] = dot(z[row], z[col])
//   h_j = relu(P[row][j] + P[col][16+j])   (b1 pre-folded)
//   weights[e] = softplus(sum_j h_j * W2[j] + b2)
// out[0:E] = adj_logits, out[E:2E] = weights.  edge_index is int32.
// Measured 42.6us — MLP head rides nearly free on the dot head's loads
// (R12 post-mortem: split into dot+mlp kernels cost 54.3us).
// ---------------------------------------------------------------------------
__global__ __launch_bounds__(256) void edge_kernel(
    const float* __restrict__ z,
    const int* __restrict__ ei,
    const float* __restrict__ W2,
    const float* __restrict__ b2,
    float* __restrict__ out,
    int E)
{
    const int t = blockIdx.x * 256 + threadIdx.x;
    const int e = t >> 3;               // edge id (grid sized exactly: e < E)
    const int l = t & 7;                // lane within 8-lane segment

    const int row = __ldg(ei + e);
    const int col = __ldg(ei + (size_t)E + e);

    // ---- issue all gathers up front ----
    const float4* zr = (const float4*)(z + (size_t)row * D);
    const float4* zc = (const float4*)(z + (size_t)col * D);
    float4 a0 = __ldg(zr + l);
    float4 a1 = __ldg(zr + l + 8);
    float4 a2 = __ldg(zr + l + 16);
    float4 a3 = __ldg(zr + l + 24);
    float4 c0 = __ldg(zc + l);
    float4 c1 = __ldg(zc + l + 8);
    float4 c2 = __ldg(zc + l + 16);
    float4 c3 = __ldg(zc + l + 24);

    float2 pa = *(const float2*)(g_P + (size_t)row * 32 + 2 * l);
    float2 pb = *(const float2*)(g_P + (size_t)col * 32 + 16 + 2 * l);
    float2 w2 = __ldg((const float2*)W2 + l);

    // ---- dot head ----
    float dot = a0.x * c0.x + a0.y * c0.y + a0.z * c0.z + a0.w * c0.w
              + a1.x * c1.x + a1.y * c1.y + a1.z * c1.z + a1.w * c1.w
              + a2.x * c2.x + a2.y * c2.y + a2.z * c2.z + a2.w * c2.w
              + a3.x * c3.x + a3.y * c3.y + a3.z * c3.z + a3.w * c3.w;
    dot += __shfl_xor_sync(0xFFFFFFFFu, dot, 1);
    dot += __shfl_xor_sync(0xFFFFFFFFu, dot, 2);
    dot += __shfl_xor_sync(0xFFFFFFFFu, dot, 4);

    // ---- MLP head ----
    float h0 = fmaxf(pa.x + pb.x, 0.f);
    float h1 = fmaxf(pa.y + pb.y, 0.f);
    float tt = h0 * w2.x + h1 * w2.y;
    tt += __shfl_xor_sync(0xFFFFFFFFu, tt, 1);
    tt += __shfl_xor_sync(0xFFFFFFFFu, tt, 2);
    tt += __shfl_xor_sync(0xFFFFFFFFu, tt, 4);

    if (l == 0) {
        out[e] = dot;
        float x = tt + __ldg(b2);
        float w = fmaxf(x, 0.f) + log1pf(expf(-fabsf(x)));
        out[(size_t)E + e] = w;
    }
}

extern "C" void kernel_launch(void* const* d_in, const int* in_sizes, int n_in,
                              void* d_out, int out_size)
{
    // metadata order: z, edge_index, W1, b1, W2, b2
    const float* z  = (const float*)d_in[0];
    const int*   ei = (const int*)d_in[1];   // int32
    const float* W1 = (const float*)d_in[2];
    const float* b1 = (const float*)d_in[3];
    const float* W2 = (const float*)d_in[4];
    const float* b2 = (const float*)d_in[5];
    float* out = (float*)d_out;

    const int N = in_sizes[0] / D;      // 100000
    const int E = in_sizes[1] / 2;      // 600000

    const int smem_bytes = (64 * D + 32 * 32 * 4) * 4;   // 48 KB
    static bool attr_set = false;
    if (!attr_set) {
        cudaFuncSetAttribute(proj_kernel,
                             cudaFuncAttributeMaxDynamicSharedMemorySize,
                             smem_bytes);
        attr_set = true;
    }

    proj_kernel<<<(N + 63) / 64, 256, smem_bytes>>>(z, W1, b1, N);

    long long threads = (long long)E * 8;   // 4.8M -> grid 18750 exact
    int grid = (int)((threads + 255) / 256);
    edge_kernel<<<grid, 256>>>(z, ei, W2, b2, out, E);
}

// round 14
// speedup vs baseline: 1.4624x; 1.4624x over previous
#include <cuda_runtime.h>
#include <cuda_bf16.h>
#include <cstdint>

#define D 128          // feature dim
#define H 16           // hidden dim
#define NMAX 100000    // max nodes (scratch sizing)

// Per-node projections P[n][k]: k in [0,16) = z[n] @ W1[0:128,:],
// k in [16,32) = z[n] @ W1[128:256,:] + b1[k-16]  (b1 folded in).
__device__ float g_P[(size_t)NMAX * 32];

// ---------------------------------------------------------------------------
// Kernel 1: P = [z @ W1a , z @ W1b + b1]
// 256 thr = 8 warps; 64 nodes/block, 8 nodes/warp; 48KB smem -> 4 CTA/SM.
// lane = output k. W staged wt4[d4][k] (contiguous in k, conflict-free).
// z main-loop reads are uniform broadcasts. fma.rn.f32x2 with operands
// loaded directly into b64 pairs (ld.shared.v2.b64), no mov packing.
// ---------------------------------------------------------------------------
__global__ __launch_bounds__(256) void proj_kernel(
    const float* __restrict__ z,
    const float* __restrict__ W1,
    const float* __restrict__ b1,
    int N)
{
    extern __shared__ float smem[];
    float*  zs  = smem;                      // [64][128]  32KB
    float4* wt4 = (float4*)(smem + 64 * D);  // [32 d4][32 k] 16KB

    const int tid = threadIdx.x;
    const int nb  = blockIdx.x * 64;

    for (int idx = tid; idx < 32 * 32; idx += 256) {
        int d4 = idx >> 5;
        int k  = idx & 31;
        int d0 = d4 * 4;
        float4 w;
        if (k < 16) {
            w.x = W1[(d0 + 0) * H + k];
            w.y = W1[(d0 + 1) * H + k];
            w.z = W1[(d0 + 2) * H + k];
            w.w = W1[(d0 + 3) * H + k];
        } else {
            int kk = k - 16;
            w.x = W1[(D + d0 + 0) * H + kk];
            w.y = W1[(D + d0 + 1) * H + kk];
            w.z = W1[(D + d0 + 2) * H + kk];
            w.w = W1[(D + d0 + 3) * H + kk];
        }
        wt4[idx] = w;
    }

    {
        const float4* zg = (const float4*)(z + (size_t)nb * D);
        float4* zs4 = (float4*)zs;
        #pragma unroll
        for (int it = 0; it < 8; it++) {
            int idx = it * 256 + tid;
            int r = idx >> 5;
            if (nb + r < N) zs4[idx] = zg[idx];
            else            zs4[idx] = make_float4(0.f, 0.f, 0.f, 0.f);
        }
    }
    __syncthreads();

    const int lane = tid & 31;          // output index k
    const int warp = tid >> 5;
    const int n0   = warp * 8;          // 8 nodes per warp

    unsigned long long acc[8];
    #pragma unroll
    for (int j = 0; j < 8; j++) acc[j] = 0ULL;

    const unsigned int zsh = (unsigned int)__cvta_generic_to_shared(zs + n0 * D);
    const unsigned int wsh = (unsigned int)__cvta_generic_to_shared(wt4) + lane * 16u;

    #pragma unroll 8
    for (int d4 = 0; d4 < 32; d4++) {
        unsigned long long wlo, whi;
        asm("ld.shared.v2.b64 {%0, %1}, [%2];"
            : "=l"(wlo), "=l"(whi) : "r"(wsh + d4 * 512u));   // conflict-free
        #pragma unroll
        for (int j = 0; j < 8; j++) {
            unsigned long long vlo, vhi;
            asm("ld.shared.v2.b64 {%0, %1}, [%2];"
                : "=l"(vlo), "=l"(vhi)
                : "r"(zsh + j * 512u + d4 * 16u));            // broadcast
            asm("fma.rn.f32x2 %0, %1, %2, %0;" : "+l"(acc[j]) : "l"(vlo), "l"(wlo));
            asm("fma.rn.f32x2 %0, %1, %2, %0;" : "+l"(acc[j]) : "l"(vhi), "l"(whi));
        }
    }

    float bb = (lane >= 16) ? __ldg(b1 + lane - 16) : 0.f;

    #pragma unroll
    for (int j = 0; j < 8; j++) {
        int n = nb + n0 + j;
        if (n < N) {
            float lo, hi;
            asm("mov.b64 {%0, %1}, %2;" : "=f"(lo), "=f"(hi) : "l"(acc[j]));
            g_P[(size_t)n * 32 + lane] = lo + hi + bb;
        }
    }
}

// ---------------------------------------------------------------------------
// Kernel 2 (R10 fused edge, exact form incl. tail clamp): 8 lanes per edge.
//   adj_logits[e] = dot(z[row], z[col])
//   h_j = relu(P[row][j] + P[col][16+j])   (b1 pre-folded)
//   weights[e] = softplus(sum_j h_j * W2[j] + b2)
// out[0:E] = adj_logits, out[E:2E] = weights.  edge_index is int32.
// ---------------------------------------------------------------------------
__global__ __launch_bounds__(256) void edge_kernel(
    const float* __restrict__ z,
    const int* __restrict__ ei,
    const float* __restrict__ W2,
    const float* __restrict__ b2,
    float* __restrict__ out,
    int E)
{
    const int t = blockIdx.x * 256 + threadIdx.x;
    const int e = t >> 3;               // edge id
    const int l = t & 7;                // lane within 8-lane segment
    const bool valid = (e < E);
    const int ec = valid ? e : (E - 1);

    const int row = __ldg(ei + ec);
    const int col = __ldg(ei + (size_t)E + ec);

    // ---- issue all gathers up front ----
    const float4* zr = (const float4*)(z + (size_t)row * D);
    const float4* zc = (const float4*)(z + (size_t)col * D);
    float4 a0 = __ldg(zr + l);
    float4 a1 = __ldg(zr + l + 8);
    float4 a2 = __ldg(zr + l + 16);
    float4 a3 = __ldg(zr + l + 24);
    float4 c0 = __ldg(zc + l);
    float4 c1 = __ldg(zc + l + 8);
    float4 c2 = __ldg(zc + l + 16);
    float4 c3 = __ldg(zc + l + 24);

    float2 pa = *(const float2*)(g_P + (size_t)row * 32 + 2 * l);
    float2 pb = *(const float2*)(g_P + (size_t)col * 32 + 16 + 2 * l);
    float2 w2 = __ldg((const float2*)W2 + l);
    float  bb2 = __ldg(b2);

    // ---- dot head ----
    float dot = a0.x * c0.x + a0.y * c0.y + a0.z * c0.z + a0.w * c0.w
              + a1.x * c1.x + a1.y * c1.y + a1.z * c1.z + a1.w * c1.w
              + a2.x * c2.x + a2.y * c2.y + a2.z * c2.z + a2.w * c2.w
              + a3.x * c3.x + a3.y * c3.y + a3.z * c3.z + a3.w * c3.w;
    dot += __shfl_xor_sync(0xFFFFFFFFu, dot, 1);
    dot += __shfl_xor_sync(0xFFFFFFFFu, dot, 2);
    dot += __shfl_xor_sync(0xFFFFFFFFu, dot, 4);

    // ---- MLP head ----
    float h0 = fmaxf(pa.x + pb.x, 0.f);
    float h1 = fmaxf(pa.y + pb.y, 0.f);
    float tt = h0 * w2.x + h1 * w2.y;
    tt += __shfl_xor_sync(0xFFFFFFFFu, tt, 1);
    tt += __shfl_xor_sync(0xFFFFFFFFu, tt, 2);
    tt += __shfl_xor_sync(0xFFFFFFFFu, tt, 4);

    if (l == 0 && valid) {
        out[e] = dot;
        float x = tt + bb2;
        float w = fmaxf(x, 0.f) + log1pf(expf(-fabsf(x)));
        out[(size_t)E + e] = w;
    }
}

extern "C" void kernel_launch(void* const* d_in, const int* in_sizes, int n_in,
                              void* d_out, int out_size)
{
    // metadata order: z, edge_index, W1, b1, W2, b2
    const float* z  = (const float*)d_in[0];
    const int*   ei = (const int*)d_in[1];   // int32
    const float* W1 = (const float*)d_in[2];
    const float* b1 = (const float*)d_in[3];
    const float* W2 = (const float*)d_in[4];
    const float* b2 = (const float*)d_in[5];
    float* out = (float*)d_out;

    const int N = in_sizes[0] / D;      // 100000
    const int E = in_sizes[1] / 2;      // 600000

    const int smem_bytes = (64 * D + 32 * 32 * 4) * 4;   // 48 KB
    static bool attr_set = false;
    if (!attr_set) {
        cudaFuncSetAttribute(proj_kernel,
                             cudaFuncAttributeMaxDynamicSharedMemorySize,
                             smem_bytes);
        attr_set = true;
    }

    proj_kernel<<<(N + 63) / 64, 256, smem_bytes>>>(z, W1, b1, N);

    long long threads = (long long)E * 8;   // 4.8M -> grid 18750
    int grid = (int)((threads + 255) / 256);
    edge_kernel<<<grid, 256>>>(z, ei, W2, b2, out, E);
}